// round 1
// baseline (speedup 1.0000x reference)
#include <cuda_runtime.h>
#include <math.h>

#define N_   8
#define CIN  512
#define MID  256
#define OUTC 256
#define H_   56
#define W_   56
#define P_   3136
#define PY_  784
#define K_   9
#define EPSF 1e-5f

// Scratch (static device globals; no allocation allowed)
__device__ float g_nhwc[(size_t)N_ * P_ * MID];     // xf in NHWC for gather
__device__ float g_off[(size_t)N_ * 18 * P_];       // offsets
__device__ float g_xf_scratch[(size_t)N_ * MID * P_]; // xf NCHW fallback

// ---------------------------------------------------------------------------
// Kernel 1: conv1(1x1,512->256) + BN1 + nearest-upsample(y) + attention fuse
// Produces xf in NCHW (to xf_nchw) and NHWC (to g_nhwc).
// Block: 32 pixels, 256 threads. Thread handles (m, m+128) x 16 pixels.
// ---------------------------------------------------------------------------
__global__ void k1_fuse(const float* __restrict__ x, const float* __restrict__ y,
                        const float* __restrict__ w1,
                        const float* __restrict__ g1, const float* __restrict__ b1,
                        const float* __restrict__ mu1, const float* __restrict__ v1,
                        const float* __restrict__ attw, const float* __restrict__ attb,
                        float* __restrict__ xf_nchw)
{
    extern __shared__ float sm[];
    float* xs   = sm;               // 16*32      = 512
    float* ws   = xs + 512;         // 256*17     = 4352
    float* xm_s = ws + 4352;        // 256*33     = 8448
    float* yu_s = xm_s + 8448;      // 256*33     = 8448
    float* aw   = yu_s + 8448;      // 1024
    float* zs   = aw + 1024;        // 64
    int*   sidx = (int*)(zs + 64);  // 32

    const int n   = blockIdx.y;
    const int p0  = blockIdx.x * 32;
    const int tid = threadIdx.x;
    const int mlo = tid & 127;
    const int pb  = (tid >> 7) * 16;

    float acc0[16], acc1[16];
#pragma unroll
    for (int j = 0; j < 16; j++) { acc0[j] = 0.f; acc1[j] = 0.f; }

    for (int i = tid; i < 1024; i += 256) aw[i] = attw[i];
    if (tid < 32) {
        int pg = p0 + tid;
        int hh = pg / 56, ww = pg % 56;
        sidx[tid] = (hh >> 1) * 28 + (ww >> 1);
    }

    const float* xb = x + (size_t)n * CIN * P_ + p0;
    for (int c0 = 0; c0 < CIN; c0 += 16) {
        for (int i = tid; i < 512; i += 256) {
            int c = i >> 5, p = i & 31;
            xs[c * 32 + p] = xb[(size_t)(c0 + c) * P_ + p];
        }
        for (int i = tid; i < 4096; i += 256) {
            int m = i >> 4, cc = i & 15;
            ws[m * 17 + cc] = w1[m * 512 + c0 + cc];
        }
        __syncthreads();
#pragma unroll
        for (int cc = 0; cc < 16; cc++) {
            float wv0 = ws[mlo * 17 + cc];
            float wv1 = ws[(mlo + 128) * 17 + cc];
#pragma unroll
            for (int j = 0; j < 16; j++) {
                float xv = xs[cc * 32 + pb + j];
                acc0[j] = fmaf(wv0, xv, acc0[j]);
                acc1[j] = fmaf(wv1, xv, acc1[j]);
            }
        }
        __syncthreads();
    }

    // BN1
    float s0 = g1[mlo] * rsqrtf(v1[mlo] + EPSF);
    float bb0 = b1[mlo] - mu1[mlo] * s0;
    float s1 = g1[mlo + 128] * rsqrtf(v1[mlo + 128] + EPSF);
    float bb1 = b1[mlo + 128] - mu1[mlo + 128] * s1;
#pragma unroll
    for (int j = 0; j < 16; j++) {
        acc0[j] = fmaf(acc0[j], s0, bb0);
        acc1[j] = fmaf(acc1[j], s1, bb1);
        xm_s[mlo * 33 + pb + j] = acc0[j];
        xm_s[(mlo + 128) * 33 + pb + j] = acc1[j];
    }
    __syncthreads();

    // upsampled y
    const float* yb = y + (size_t)n * MID * PY_;
    for (int i = tid; i < 8192; i += 256) {
        int m = i >> 5, p = i & 31;
        yu_s[m * 33 + p] = yb[(size_t)m * PY_ + sidx[p]];
    }
    __syncthreads();

    // attention: z = sigmoid(att_w @ [xm;yu] + att_b)  (2 outputs per pixel)
    int wid = tid >> 5, lane = tid & 31;
    for (int pi = 0; pi < 4; pi++) {
        int p = wid * 4 + pi;
        float t0 = 0.f, t1 = 0.f;
#pragma unroll
        for (int j = 0; j < 8; j++) {
            int m = lane + j * 32;
            float xmv = xm_s[m * 33 + p];
            float yuv = yu_s[m * 33 + p];
            t0 += aw[m] * xmv + aw[256 + m] * yuv;
            t1 += aw[512 + m] * xmv + aw[768 + m] * yuv;
        }
#pragma unroll
        for (int o = 16; o > 0; o >>= 1) {
            t0 += __shfl_xor_sync(0xffffffffu, t0, o);
            t1 += __shfl_xor_sync(0xffffffffu, t1, o);
        }
        if (lane == 0) {
            zs[p]      = 1.f / (1.f + expf(-(t0 + attb[0])));
            zs[32 + p] = 1.f / (1.f + expf(-(t1 + attb[1])));
        }
    }
    __syncthreads();

    // xf = xm*z0 + yu*z1 ; write NCHW + NHWC
    float* xo0 = xf_nchw + ((size_t)(n * 256 + mlo)) * P_ + p0 + pb;
    float* xo1 = xf_nchw + ((size_t)(n * 256 + mlo + 128)) * P_ + p0 + pb;
    float* nh  = g_nhwc + ((size_t)n * P_ + p0 + pb) * 256;
#pragma unroll
    for (int j = 0; j < 16; j++) {
        int p = pb + j;
        float z0 = zs[p], z1 = zs[32 + p];
        float f0 = fmaf(acc0[j], z0, yu_s[mlo * 33 + p] * z1);
        float f1 = fmaf(acc1[j], z0, yu_s[(mlo + 128) * 33 + p] * z1);
        xo0[j] = f0;
        xo1[j] = f1;
        nh[(size_t)j * 256 + mlo] = f0;
        nh[(size_t)j * 256 + mlo + 128] = f1;
    }
}

// ---------------------------------------------------------------------------
// Kernel 2: offset conv3x3 (256 -> 18), pad 1. One block per (h row, n).
// ---------------------------------------------------------------------------
__global__ void k2_off(const float* __restrict__ xf, const float* __restrict__ ow)
{
    __shared__ float xr[32 * 3 * 58];   // [c][row][col+1], chunk of 32 channels
    __shared__ float wr[18 * 289];      // [o][c*9+k], padded rows

    const int h = blockIdx.x, n = blockIdx.y;
    const int tid = threadIdx.x;
    const int o = tid / 14, wg = tid % 14, wbase = wg * 4;

    float acc[4] = {0.f, 0.f, 0.f, 0.f};

    for (int c0 = 0; c0 < 256; c0 += 32) {
        for (int i = tid; i < 5568; i += 256) {
            int c = i / 174, r = (i % 174) / 58, colp = i % 58;
            int row = h + r - 1, col = colp - 1;
            float v = 0.f;
            if (row >= 0 && row < 56 && col >= 0 && col < 56)
                v = xf[((size_t)(n * 256 + c0 + c)) * P_ + row * 56 + col];
            xr[i] = v;
        }
        for (int i = tid; i < 5184; i += 256) {
            int oo = i / 288, rem = i % 288;
            wr[oo * 289 + rem] = ow[(size_t)oo * 2304 + c0 * 9 + rem];
        }
        __syncthreads();
        if (tid < 252) {
            for (int c = 0; c < 32; c++) {
#pragma unroll
                for (int ky = 0; ky < 3; ky++) {
                    float xrow[6];
#pragma unroll
                    for (int u = 0; u < 6; u++)
                        xrow[u] = xr[c * 174 + ky * 58 + wbase + u];
#pragma unroll
                    for (int kx = 0; kx < 3; kx++) {
                        float wv = wr[o * 289 + c * 9 + ky * 3 + kx];
#pragma unroll
                        for (int j = 0; j < 4; j++)
                            acc[j] = fmaf(wv, xrow[kx + j], acc[j]);
                    }
                }
            }
        }
        __syncthreads();
    }
    if (tid < 252) {
        float* ob = g_off + ((size_t)(n * 18 + o)) * P_ + h * 56 + wbase;
#pragma unroll
        for (int j = 0; j < 4; j++) ob[j] = acc[j];
    }
}

// ---------------------------------------------------------------------------
// Kernel 3: deformable conv (bilinear gather from NHWC xf) + GEMM + BN2
// Block: 16 pixels. Phase A: sample s[c*9+k][p] into SMEM (157KB).
// Phase B: out[o][p] = sum_ck w[o][ck]*s[ck][p], 2 o's x 8 p per thread.
// ---------------------------------------------------------------------------
__global__ void k3_dcn(const float* __restrict__ dw,
                       const float* __restrict__ g2, const float* __restrict__ b2,
                       const float* __restrict__ mu2, const float* __restrict__ v2,
                       float* __restrict__ out)
{
    extern __shared__ float sm[];
    float* s_tile = sm;                     // 2304*17 = 39168
    float* w_tile = s_tile + 2304 * 17;     // 256*17  = 4352
    float* mw     = w_tile + 4352;          // 4*144 tap weights
    int*   mc     = (int*)(mw + 576);       // 4*144 clamped coords (y0,y1,x0,x1)

    const int n  = blockIdx.y;
    const int p0 = blockIdx.x * 16;
    const int tid = threadIdx.x;

    if (tid < 144) {
        int p = tid / 9, k = tid % 9;
        int pg = p0 + p;
        int ph = pg / 56, pw = pg % 56;
        float dy = g_off[((size_t)(n * 18 + 2 * k)) * P_ + pg];
        float dx = g_off[((size_t)(n * 18 + 2 * k + 1)) * P_ + pg];
        float sy = (float)(ph - 1 + k / 3) + dy;
        float sx = (float)(pw - 1 + k % 3) + dx;
        float y0f = floorf(sy), x0f = floorf(sx);
        float wy1 = sy - y0f, wx1 = sx - x0f;
        int iy0 = (int)y0f, ix0 = (int)x0f;
        bool vy0 = (iy0 >= 0) && (iy0 <= 55);
        bool vy1 = (iy0 + 1 >= 0) && (iy0 + 1 <= 55);
        bool vx0 = (ix0 >= 0) && (ix0 <= 55);
        bool vx1 = (ix0 + 1 >= 0) && (ix0 + 1 <= 55);
        float w00 = (1.f - wy1) * (1.f - wx1);
        float w01 = (1.f - wy1) * wx1;
        float w10 = wy1 * (1.f - wx1);
        float w11 = wy1 * wx1;
        mw[tid]       = (vy0 && vx0) ? w00 : 0.f;
        mw[144 + tid] = (vy0 && vx1) ? w01 : 0.f;
        mw[288 + tid] = (vy1 && vx0) ? w10 : 0.f;
        mw[432 + tid] = (vy1 && vx1) ? w11 : 0.f;
        mc[tid]       = min(max(iy0, 0), 55);
        mc[144 + tid] = min(max(iy0 + 1, 0), 55);
        mc[288 + tid] = min(max(ix0, 0), 55);
        mc[432 + tid] = min(max(ix0 + 1, 0), 55);
    }
    __syncthreads();

    // Phase A: bilinear sampling, c = tid (coalesced NHWC reads)
    const float* nh = g_nhwc + (size_t)n * P_ * 256;
    const int c = tid;
    for (int pk = 0; pk < 144; pk++) {
        int k = pk % 9, p = pk / 9;
        int y0c = mc[pk], y1c = mc[144 + pk], x0c = mc[288 + pk], x1c = mc[432 + pk];
        float w00 = mw[pk], w01 = mw[144 + pk], w10 = mw[288 + pk], w11 = mw[432 + pk];
        float v = w00 * nh[(size_t)(y0c * 56 + x0c) * 256 + c]
                + w01 * nh[(size_t)(y0c * 56 + x1c) * 256 + c]
                + w10 * nh[(size_t)(y1c * 56 + x0c) * 256 + c]
                + w11 * nh[(size_t)(y1c * 56 + x1c) * 256 + c];
        s_tile[(c * 9 + k) * 17 + p] = v;
    }
    __syncthreads();

    // Phase B: GEMM  out[o][p] = sum_ck dw[o][ck] * s[ck][p]
    const int olo = tid & 127, pb = (tid >> 7) * 8;
    float a0[8], a1[8];
#pragma unroll
    for (int j = 0; j < 8; j++) { a0[j] = 0.f; a1[j] = 0.f; }

    for (int ck0 = 0; ck0 < 2304; ck0 += 16) {
        for (int i = tid; i < 4096; i += 256) {
            int o = i >> 4, cc = i & 15;
            w_tile[o * 17 + cc] = dw[(size_t)o * 2304 + ck0 + cc];
        }
        __syncthreads();
#pragma unroll
        for (int cc = 0; cc < 16; cc++) {
            float wv0 = w_tile[olo * 17 + cc];
            float wv1 = w_tile[(olo + 128) * 17 + cc];
#pragma unroll
            for (int j = 0; j < 8; j++) {
                float xv = s_tile[(ck0 + cc) * 17 + pb + j];
                a0[j] = fmaf(wv0, xv, a0[j]);
                a1[j] = fmaf(wv1, xv, a1[j]);
            }
        }
        __syncthreads();
    }

    float sc0 = g2[olo] * rsqrtf(v2[olo] + EPSF);
    float bi0 = b2[olo] - mu2[olo] * sc0;
    float sc1 = g2[olo + 128] * rsqrtf(v2[olo + 128] + EPSF);
    float bi1 = b2[olo + 128] - mu2[olo + 128] * sc1;
    float* o0 = out + ((size_t)(n * 256 + olo)) * P_ + p0 + pb;
    float* o1 = out + ((size_t)(n * 256 + olo + 128)) * P_ + p0 + pb;
#pragma unroll
    for (int j = 0; j < 8; j++) {
        o0[j] = fmaf(a0[j], sc0, bi0);
        o1[j] = fmaf(a1[j], sc1, bi1);
    }
}

// ---------------------------------------------------------------------------
extern "C" void kernel_launch(void* const* d_in, const int* in_sizes, int n_in,
                              void* d_out, int out_size)
{
    const float* x       = (const float*)d_in[0];
    const float* y       = (const float*)d_in[1];
    const float* conv1_w = (const float*)d_in[2];
    const float* bn1_g   = (const float*)d_in[3];
    const float* bn1_b   = (const float*)d_in[4];
    const float* bn1_m   = (const float*)d_in[5];
    const float* bn1_v   = (const float*)d_in[6];
    const float* att_w   = (const float*)d_in[7];
    const float* att_b   = (const float*)d_in[8];
    const float* off_w   = (const float*)d_in[9];
    const float* dcn_w   = (const float*)d_in[10];
    const float* bn2_g   = (const float*)d_in[11];
    const float* bn2_b   = (const float*)d_in[12];
    const float* bn2_m   = (const float*)d_in[13];
    const float* bn2_v   = (const float*)d_in[14];

    float* out = (float*)d_out;
    const size_t one = (size_t)N_ * OUTC * P_;  // 6,422,528

    float* xf_nchw;
    if ((size_t)out_size >= 2 * one) {
        xf_nchw = out + one;  // tuple (out, xf) flattened
    } else {
        void* p = nullptr;
        cudaGetSymbolAddress(&p, g_xf_scratch);
        xf_nchw = (float*)p;
    }

    static bool attr_done = false;
    if (!attr_done) {
        cudaFuncSetAttribute(k1_fuse, cudaFuncAttributeMaxDynamicSharedMemorySize, 96 * 1024);
        cudaFuncSetAttribute(k3_dcn, cudaFuncAttributeMaxDynamicSharedMemorySize, 184 * 1024);
        attr_done = true;
    }

    const size_t smem1 = (512 + 4352 + 8448 + 8448 + 1024 + 64 + 32) * 4; // 91,520
    k1_fuse<<<dim3(98, 8), 256, smem1>>>(x, y, conv1_w, bn1_g, bn1_b, bn1_m, bn1_v,
                                         att_w, att_b, xf_nchw);

    k2_off<<<dim3(56, 8), 256>>>(xf_nchw, off_w);

    const size_t smem3 = (2304 * 17 + 4352 + 576 + 576) * 4; // 178,688
    k3_dcn<<<dim3(196, 8), 256, smem3>>>(dcn_w, bn2_g, bn2_b, bn2_m, bn2_v, out);
}

// round 2
// speedup vs baseline: 2.6399x; 2.6399x over previous
#include <cuda_runtime.h>
#include <math.h>

#define N_   8
#define CIN  512
#define MID  256
#define OUTC 256
#define H_   56
#define W_   56
#define P_   3136
#define PY_  784
#define K_   9
#define EPSF 1e-5f

// Scratch (static device globals; no allocation allowed)
__device__ float g_nhwc[(size_t)N_ * P_ * MID];       // xf in NHWC for gather
__device__ float g_off[(size_t)N_ * 18 * P_];         // offsets
__device__ float g_xf_scratch[(size_t)N_ * MID * P_]; // xf NCHW fallback

// ---------------------------------------------------------------------------
// Kernel 1: conv1(1x1,512->256) + BN1 + nearest-upsample(y) + attention fuse
// Block: 32 pixels, 256 threads. Thread handles (m, m+128) x 16 pixels.
// Attention reduction from register accumulators (no xm smem tile).
// smem ~58.8KB -> 3 CTAs/SM.
// ---------------------------------------------------------------------------
__global__ __launch_bounds__(256, 3)
void k1_fuse(const float* __restrict__ x, const float* __restrict__ y,
             const float* __restrict__ w1,
             const float* __restrict__ g1, const float* __restrict__ b1,
             const float* __restrict__ mu1, const float* __restrict__ v1,
             const float* __restrict__ attw, const float* __restrict__ attb,
             float* __restrict__ xf_nchw)
{
    extern __shared__ float sm[];
    float* xs   = sm;               // 16*32  = 512
    float* ws   = xs + 512;         // 256*17 = 4352
    float* yu_s = ws + 4352;        // 256*33 = 8448
    float* aw   = yu_s + 8448;      // 1024
    float* red  = aw + 1024;        // 8 warps * 16 j * 2 = 256
    float* zs   = red + 256;        // 64
    // total = 14656 floats = 58,624 B

    const int n   = blockIdx.y;
    const int p0  = blockIdx.x * 32;
    const int tid = threadIdx.x;
    const int mlo = tid & 127;
    const int pb  = (tid >> 7) * 16;
    const int wid = tid >> 5;
    const int lane = tid & 31;

    float acc0[16], acc1[16];
#pragma unroll
    for (int j = 0; j < 16; j++) { acc0[j] = 0.f; acc1[j] = 0.f; }

    for (int i = tid; i < 1024; i += 256) aw[i] = attw[i];

    // preload upsampled y tile (coalesced-ish, independent of main loop)
    {
        const float* yb = y + (size_t)n * MID * PY_;
        for (int i = tid; i < 8192; i += 256) {
            int m = i >> 5, p = i & 31;
            int pgl = p0 + p;
            int hh = pgl / 56, ww = pgl % 56;
            int si = (hh >> 1) * 28 + (ww >> 1);
            yu_s[m * 33 + p] = yb[(size_t)m * PY_ + si];
        }
    }

    const float* xb = x + (size_t)n * CIN * P_ + p0;
    for (int c0 = 0; c0 < CIN; c0 += 16) {
        for (int i = tid; i < 512; i += 256) {
            int c = i >> 5, p = i & 31;
            xs[c * 32 + p] = xb[(size_t)(c0 + c) * P_ + p];
        }
        for (int i = tid; i < 4096; i += 256) {
            int m = i >> 4, cc = i & 15;
            ws[m * 17 + cc] = w1[m * 512 + c0 + cc];
        }
        __syncthreads();
#pragma unroll
        for (int cc = 0; cc < 16; cc++) {
            float wv0 = ws[mlo * 17 + cc];
            float wv1 = ws[(mlo + 128) * 17 + cc];
            const float4* xp = (const float4*)(xs + cc * 32 + pb);
#pragma unroll
            for (int u = 0; u < 4; u++) {
                float4 xv = xp[u];
                acc0[u*4+0] = fmaf(wv0, xv.x, acc0[u*4+0]);
                acc0[u*4+1] = fmaf(wv0, xv.y, acc0[u*4+1]);
                acc0[u*4+2] = fmaf(wv0, xv.z, acc0[u*4+2]);
                acc0[u*4+3] = fmaf(wv0, xv.w, acc0[u*4+3]);
                acc1[u*4+0] = fmaf(wv1, xv.x, acc1[u*4+0]);
                acc1[u*4+1] = fmaf(wv1, xv.y, acc1[u*4+1]);
                acc1[u*4+2] = fmaf(wv1, xv.z, acc1[u*4+2]);
                acc1[u*4+3] = fmaf(wv1, xv.w, acc1[u*4+3]);
            }
        }
        __syncthreads();
    }

    // BN1 into accumulators
    {
        float s0 = g1[mlo] * rsqrtf(v1[mlo] + EPSF);
        float bb0 = b1[mlo] - mu1[mlo] * s0;
        float s1 = g1[mlo + 128] * rsqrtf(v1[mlo + 128] + EPSF);
        float bb1 = b1[mlo + 128] - mu1[mlo + 128] * s1;
#pragma unroll
        for (int j = 0; j < 16; j++) {
            acc0[j] = fmaf(acc0[j], s0, bb0);
            acc1[j] = fmaf(acc1[j], s1, bb1);
        }
    }

    // attention partials: t0/t1[p] = sum_m (aw[m]*xm + aw[256+m]*yu), reduce
    {
        float a00 = aw[mlo], a01 = aw[mlo + 128];
        float a10 = aw[256 + mlo], a11 = aw[256 + mlo + 128];
        float a20 = aw[512 + mlo], a21 = aw[512 + mlo + 128];
        float a30 = aw[768 + mlo], a31 = aw[768 + mlo + 128];
#pragma unroll
        for (int j = 0; j < 16; j++) {
            int p = pb + j;
            float yv0 = yu_s[mlo * 33 + p];
            float yv1 = yu_s[(mlo + 128) * 33 + p];
            float t0 = a00 * acc0[j] + a01 * acc1[j] + a10 * yv0 + a11 * yv1;
            float t1 = a20 * acc0[j] + a21 * acc1[j] + a30 * yv0 + a31 * yv1;
#pragma unroll
            for (int o = 16; o > 0; o >>= 1) {
                t0 += __shfl_xor_sync(0xffffffffu, t0, o);
                t1 += __shfl_xor_sync(0xffffffffu, t1, o);
            }
            if (lane == 0) {
                red[(wid * 16 + j) * 2 + 0] = t0;
                red[(wid * 16 + j) * 2 + 1] = t1;
            }
        }
    }
    __syncthreads();
    if (tid < 32) {
        int grp = tid >> 4, j = tid & 15;
        float s0 = 0.f, s1 = 0.f;
#pragma unroll
        for (int w = 0; w < 4; w++) {
            s0 += red[((grp * 4 + w) * 16 + j) * 2 + 0];
            s1 += red[((grp * 4 + w) * 16 + j) * 2 + 1];
        }
        zs[tid]      = 1.f / (1.f + expf(-(s0 + attb[0])));
        zs[32 + tid] = 1.f / (1.f + expf(-(s1 + attb[1])));
    }
    __syncthreads();

    // xf = xm*z0 + yu*z1 ; write NCHW + NHWC
    float* xo0 = xf_nchw + ((size_t)(n * 256 + mlo)) * P_ + p0 + pb;
    float* xo1 = xf_nchw + ((size_t)(n * 256 + mlo + 128)) * P_ + p0 + pb;
    float* nh  = g_nhwc + ((size_t)n * P_ + p0 + pb) * 256;
#pragma unroll
    for (int j = 0; j < 16; j++) {
        int p = pb + j;
        float z0 = zs[p], z1 = zs[32 + p];
        float f0 = fmaf(acc0[j], z0, yu_s[mlo * 33 + p] * z1);
        float f1 = fmaf(acc1[j], z0, yu_s[(mlo + 128) * 33 + p] * z1);
        xo0[j] = f0;
        xo1[j] = f1;
        nh[(size_t)j * 256 + mlo] = f0;
        nh[(size_t)j * 256 + mlo + 128] = f1;
    }
}

// ---------------------------------------------------------------------------
// Kernel 2: offset conv3x3 (256 -> 18), pad 1. One block per (h row, n).
// Row pitch 60 -> vectorized LDS.128 reads.
// ---------------------------------------------------------------------------
__global__ __launch_bounds__(256, 4)
void k2_off(const float* __restrict__ xf, const float* __restrict__ ow)
{
    __shared__ float xr[32 * 3 * 60];   // [c][row][col], pitch 60
    __shared__ float wr[18 * 289];      // [o][c*9+k]

    const int h = blockIdx.x, n = blockIdx.y;
    const int tid = threadIdx.x;
    const int o = tid / 14, wg = tid % 14, wbase = wg * 4;

    float acc[4] = {0.f, 0.f, 0.f, 0.f};

    for (int c0 = 0; c0 < 256; c0 += 32) {
        for (int i = tid; i < 5568; i += 256) {
            int c = i / 174, rem = i % 174, r = rem / 58, colp = rem % 58;
            int row = h + r - 1, col = colp - 1;
            float v = 0.f;
            if (row >= 0 && row < 56 && col >= 0 && col < 56)
                v = xf[((size_t)(n * 256 + c0 + c)) * P_ + row * 56 + col];
            xr[c * 180 + r * 60 + colp] = v;
        }
        for (int i = tid; i < 5184; i += 256) {
            int oo = i / 288, rem = i % 288;
            wr[oo * 289 + rem] = ow[(size_t)oo * 2304 + c0 * 9 + rem];
        }
        __syncthreads();
        if (tid < 252) {
            for (int c = 0; c < 32; c++) {
#pragma unroll
                for (int ky = 0; ky < 3; ky++) {
                    const float4* rp = (const float4*)(xr + c * 180 + ky * 60 + wbase);
                    float4 A = rp[0], B = rp[1];
                    float xrow[6] = {A.x, A.y, A.z, A.w, B.x, B.y};
#pragma unroll
                    for (int kx = 0; kx < 3; kx++) {
                        float wv = wr[o * 289 + c * 9 + ky * 3 + kx];
#pragma unroll
                        for (int j = 0; j < 4; j++)
                            acc[j] = fmaf(wv, xrow[kx + j], acc[j]);
                    }
                }
            }
        }
        __syncthreads();
    }
    if (tid < 252) {
        float* ob = g_off + ((size_t)(n * 18 + o)) * P_ + h * 56 + wbase;
#pragma unroll
        for (int j = 0; j < 4; j++) ob[j] = acc[j];
    }
}

// ---------------------------------------------------------------------------
// Kernel 3: deformable conv + GEMM + BN2.
// Block = 32 pixels, 256 threads. K chunked 4 x (64c x 9k = 576 rows).
// smem ~109.6KB -> 2 CTAs/SM. Inner: 2 LDS + 4 LDS.128 per 32 FFMA.
// ---------------------------------------------------------------------------
__global__ __launch_bounds__(256, 2)
void k3_dcn(const float* __restrict__ dw,
            const float* __restrict__ g2, const float* __restrict__ b2,
            const float* __restrict__ mu2, const float* __restrict__ v2,
            float* __restrict__ out)
{
    extern __shared__ float sm[];
    float* s_chunk = sm;                    // 576*36 = 20736
    float* w_tile  = s_chunk + 576 * 36;    // 256*17 = 4352
    float* mw4     = w_tile + 4352;         // 288*4  = 1152
    int*   mo4     = (int*)(mw4 + 1152);    // 288*4  = 1152
    // total = 27392 floats = 109,568 B

    const int n  = blockIdx.y;
    const int p0 = blockIdx.x * 32;
    const int tid = threadIdx.x;

    // per-(pixel,k) bilinear metadata
    for (int e = tid; e < 288; e += 256) {
        int p = e / 9, k = e - p * 9;
        int pg = p0 + p;
        int ph = pg / 56, pw = pg % 56;
        float dy = g_off[((size_t)(n * 18 + 2 * k)) * P_ + pg];
        float dx = g_off[((size_t)(n * 18 + 2 * k + 1)) * P_ + pg];
        float sy = (float)(ph - 1 + k / 3) + dy;
        float sx = (float)(pw - 1 + k % 3) + dx;
        float y0f = floorf(sy), x0f = floorf(sx);
        float wy1 = sy - y0f, wx1 = sx - x0f;
        int iy0 = (int)y0f, ix0 = (int)x0f;
        bool vy0 = (iy0 >= 0) && (iy0 <= 55);
        bool vy1 = (iy0 + 1 >= 0) && (iy0 + 1 <= 55);
        bool vx0 = (ix0 >= 0) && (ix0 <= 55);
        bool vx1 = (ix0 + 1 >= 0) && (ix0 + 1 <= 55);
        int y0c = min(max(iy0, 0), 55),     y1c = min(max(iy0 + 1, 0), 55);
        int x0c = min(max(ix0, 0), 55),     x1c = min(max(ix0 + 1, 0), 55);
        mw4[e * 4 + 0] = (vy0 && vx0) ? (1.f - wy1) * (1.f - wx1) : 0.f;
        mw4[e * 4 + 1] = (vy0 && vx1) ? (1.f - wy1) * wx1 : 0.f;
        mw4[e * 4 + 2] = (vy1 && vx0) ? wy1 * (1.f - wx1) : 0.f;
        mw4[e * 4 + 3] = (vy1 && vx1) ? wy1 * wx1 : 0.f;
        mo4[e * 4 + 0] = (y0c * 56 + x0c) * 256;
        mo4[e * 4 + 1] = (y0c * 56 + x1c) * 256;
        mo4[e * 4 + 2] = (y1c * 56 + x0c) * 256;
        mo4[e * 4 + 3] = (y1c * 56 + x1c) * 256;
    }
    __syncthreads();

    const float* nh = g_nhwc + (size_t)n * P_ * 256;
    const int cl  = tid & 63;          // channel-local for Phase A (coalesced)
    const int pg8 = (tid >> 6) * 8;    // 8 pixels per thread in Phase A
    const int olo = tid & 127;         // output row for GEMM
    const int phh = (tid >> 7) * 16;   // 16 pixels per thread in GEMM

    float a0[16], a1[16];
#pragma unroll
    for (int j = 0; j < 16; j++) { a0[j] = 0.f; a1[j] = 0.f; }

    for (int cb = 0; cb < 4; cb++) {
        const int c = cb * 64 + cl;
        // -------- Phase A: bilinear sampling of 64 channels x 9 taps x 32 px
        for (int k = 0; k < 9; k++) {
#pragma unroll
            for (int i = 0; i < 8; i++) {
                int p = pg8 + i;
                int e = p * 9 + k;
                float4 w = ((const float4*)mw4)[e];
                int4  oo = ((const int4*)mo4)[e];
                float v = w.x * nh[oo.x + c] + w.y * nh[oo.y + c]
                        + w.z * nh[oo.z + c] + w.w * nh[oo.w + c];
                s_chunk[(cl * 9 + k) * 36 + p] = v;
            }
        }
        __syncthreads();
        // -------- Phase B: GEMM over this chunk's 576 K-rows
        for (int kt = 0; kt < 36; kt++) {
            int ckg = cb * 576 + kt * 16;
#pragma unroll
            for (int t = 0; t < 16; t++) {
                int i = tid + t * 256;
                int o_ = i >> 4, cc = i & 15;
                w_tile[o_ * 17 + cc] = dw[(size_t)o_ * 2304 + ckg + cc];
            }
            __syncthreads();
#pragma unroll
            for (int cc = 0; cc < 16; cc++) {
                float wv0 = w_tile[olo * 17 + cc];
                float wv1 = w_tile[(olo + 128) * 17 + cc];
                const float4* xr = (const float4*)(s_chunk + (kt * 16 + cc) * 36 + phh);
#pragma unroll
                for (int u = 0; u < 4; u++) {
                    float4 xv = xr[u];
                    a0[u*4+0] = fmaf(wv0, xv.x, a0[u*4+0]);
                    a0[u*4+1] = fmaf(wv0, xv.y, a0[u*4+1]);
                    a0[u*4+2] = fmaf(wv0, xv.z, a0[u*4+2]);
                    a0[u*4+3] = fmaf(wv0, xv.w, a0[u*4+3]);
                    a1[u*4+0] = fmaf(wv1, xv.x, a1[u*4+0]);
                    a1[u*4+1] = fmaf(wv1, xv.y, a1[u*4+1]);
                    a1[u*4+2] = fmaf(wv1, xv.z, a1[u*4+2]);
                    a1[u*4+3] = fmaf(wv1, xv.w, a1[u*4+3]);
                }
            }
            __syncthreads();
        }
    }

    // BN2 + store
    float sc0 = g2[olo] * rsqrtf(v2[olo] + EPSF);
    float bi0 = b2[olo] - mu2[olo] * sc0;
    float sc1 = g2[olo + 128] * rsqrtf(v2[olo + 128] + EPSF);
    float bi1 = b2[olo + 128] - mu2[olo + 128] * sc1;
    float* o0 = out + ((size_t)(n * 256 + olo)) * P_ + p0 + phh;
    float* o1 = out + ((size_t)(n * 256 + olo + 128)) * P_ + p0 + phh;
#pragma unroll
    for (int j = 0; j < 16; j++) {
        o0[j] = fmaf(a0[j], sc0, bi0);
        o1[j] = fmaf(a1[j], sc1, bi1);
    }
}

// ---------------------------------------------------------------------------
extern "C" void kernel_launch(void* const* d_in, const int* in_sizes, int n_in,
                              void* d_out, int out_size)
{
    const float* x       = (const float*)d_in[0];
    const float* y       = (const float*)d_in[1];
    const float* conv1_w = (const float*)d_in[2];
    const float* bn1_g   = (const float*)d_in[3];
    const float* bn1_b   = (const float*)d_in[4];
    const float* bn1_m   = (const float*)d_in[5];
    const float* bn1_v   = (const float*)d_in[6];
    const float* att_w   = (const float*)d_in[7];
    const float* att_b   = (const float*)d_in[8];
    const float* off_w   = (const float*)d_in[9];
    const float* dcn_w   = (const float*)d_in[10];
    const float* bn2_g   = (const float*)d_in[11];
    const float* bn2_b   = (const float*)d_in[12];
    const float* bn2_m   = (const float*)d_in[13];
    const float* bn2_v   = (const float*)d_in[14];

    float* out = (float*)d_out;
    const size_t one = (size_t)N_ * OUTC * P_;  // 6,422,528

    float* xf_nchw;
    if ((size_t)out_size >= 2 * one) {
        xf_nchw = out + one;  // tuple (out, xf) flattened
    } else {
        void* p = nullptr;
        cudaGetSymbolAddress(&p, g_xf_scratch);
        xf_nchw = (float*)p;
    }

    // idempotent; safe to call every launch (not a stream op)
    cudaFuncSetAttribute(k1_fuse, cudaFuncAttributeMaxDynamicSharedMemorySize, 64 * 1024);
    cudaFuncSetAttribute(k3_dcn, cudaFuncAttributeMaxDynamicSharedMemorySize, 112 * 1024);

    const size_t smem1 = (512 + 4352 + 8448 + 1024 + 256 + 64) * 4; // 58,624
    k1_fuse<<<dim3(98, 8), 256, smem1>>>(x, y, conv1_w, bn1_g, bn1_b, bn1_m, bn1_v,
                                         att_w, att_b, xf_nchw);

    k2_off<<<dim3(56, 8), 256>>>(xf_nchw, off_w);

    const size_t smem3 = (576 * 36 + 4352 + 1152 + 1152) * 4; // 109,568
    k3_dcn<<<dim3(98, 8), 256, smem3>>>(dcn_w, bn2_g, bn2_b, bn2_m, bn2_v, out);
}

// round 4
// speedup vs baseline: 4.5891x; 1.7383x over previous
#include <cuda_runtime.h>
#include <math.h>
#include <stdint.h>

#define N_   8
#define CIN  512
#define MID  256
#define OUTC 256
#define H_   56
#define W_   56
#define P_   3136
#define PY_  784
#define K_   9
#define EPSF 1e-5f

// Scratch (static device globals; no allocation allowed)
__device__ float g_nhwc[(size_t)N_ * P_ * MID];       // xf in NHWC for gather
__device__ float g_off[(size_t)N_ * 18 * P_];         // offsets
__device__ float g_xf_scratch[(size_t)N_ * MID * P_]; // xf NCHW fallback
__device__ float g_wt[(size_t)OUTC * 2304];           // dcn weights, k-major, tf32-rounded

// ---------------------------------------------------------------------------
// helpers (family-safe PTX only: sm_80+ instructions)
// ---------------------------------------------------------------------------
__device__ __forceinline__ float to_tf32(float x) {
    uint32_t u;
    asm("cvt.rna.tf32.f32 %0, %1;" : "=r"(u) : "f"(x));
    return __uint_as_float(u);
}
__device__ __forceinline__ void mma_tf32(float* d, const uint32_t* a, const uint32_t* b) {
    asm volatile(
        "mma.sync.aligned.m16n8k8.row.col.f32.tf32.tf32.f32 "
        "{%0,%1,%2,%3}, {%4,%5,%6,%7}, {%8,%9}, {%0,%1,%2,%3};"
        : "+f"(d[0]), "+f"(d[1]), "+f"(d[2]), "+f"(d[3])
        : "r"(a[0]), "r"(a[1]), "r"(a[2]), "r"(a[3]), "r"(b[0]), "r"(b[1]));
}

// ---------------------------------------------------------------------------
// Kernel 0: transpose dcn weights to k-major [o][kk*256+c], tf32-rounded
// ---------------------------------------------------------------------------
__global__ void k0_wt(const float* __restrict__ dw)
{
    int o = blockIdx.x;
    for (int i = threadIdx.x; i < 2304; i += 256) {
        int kk = i >> 8, c = i & 255;
        g_wt[(size_t)o * 2304 + i] = to_tf32(dw[(size_t)o * 2304 + c * 9 + kk]);
    }
}

// ---------------------------------------------------------------------------
// Kernel 1: conv1(1x1,512->256) + BN1 + nearest-upsample(y) + attention fuse
// (unchanged from R2)
// ---------------------------------------------------------------------------
__global__ __launch_bounds__(256, 3)
void k1_fuse(const float* __restrict__ x, const float* __restrict__ y,
             const float* __restrict__ w1,
             const float* __restrict__ g1, const float* __restrict__ b1,
             const float* __restrict__ mu1, const float* __restrict__ v1,
             const float* __restrict__ attw, const float* __restrict__ attb,
             float* __restrict__ xf_nchw)
{
    extern __shared__ float sm[];
    float* xs   = sm;               // 512
    float* ws   = xs + 512;         // 4352
    float* yu_s = ws + 4352;        // 8448
    float* aw   = yu_s + 8448;      // 1024
    float* red  = aw + 1024;        // 256
    float* zs   = red + 256;        // 64

    const int n   = blockIdx.y;
    const int p0  = blockIdx.x * 32;
    const int tid = threadIdx.x;
    const int mlo = tid & 127;
    const int pb  = (tid >> 7) * 16;
    const int wid = tid >> 5;
    const int lane = tid & 31;

    float acc0[16], acc1[16];
#pragma unroll
    for (int j = 0; j < 16; j++) { acc0[j] = 0.f; acc1[j] = 0.f; }

    for (int i = tid; i < 1024; i += 256) aw[i] = attw[i];

    {
        const float* yb = y + (size_t)n * MID * PY_;
        for (int i = tid; i < 8192; i += 256) {
            int m = i >> 5, p = i & 31;
            int pgl = p0 + p;
            int hh = pgl / 56, ww = pgl % 56;
            int si = (hh >> 1) * 28 + (ww >> 1);
            yu_s[m * 33 + p] = yb[(size_t)m * PY_ + si];
        }
    }

    const float* xb = x + (size_t)n * CIN * P_ + p0;
    for (int c0 = 0; c0 < CIN; c0 += 16) {
        for (int i = tid; i < 512; i += 256) {
            int c = i >> 5, p = i & 31;
            xs[c * 32 + p] = xb[(size_t)(c0 + c) * P_ + p];
        }
        for (int i = tid; i < 4096; i += 256) {
            int m = i >> 4, cc = i & 15;
            ws[m * 17 + cc] = w1[m * 512 + c0 + cc];
        }
        __syncthreads();
#pragma unroll
        for (int cc = 0; cc < 16; cc++) {
            float wv0 = ws[mlo * 17 + cc];
            float wv1 = ws[(mlo + 128) * 17 + cc];
            const float4* xp = (const float4*)(xs + cc * 32 + pb);
#pragma unroll
            for (int u = 0; u < 4; u++) {
                float4 xv = xp[u];
                acc0[u*4+0] = fmaf(wv0, xv.x, acc0[u*4+0]);
                acc0[u*4+1] = fmaf(wv0, xv.y, acc0[u*4+1]);
                acc0[u*4+2] = fmaf(wv0, xv.z, acc0[u*4+2]);
                acc0[u*4+3] = fmaf(wv0, xv.w, acc0[u*4+3]);
                acc1[u*4+0] = fmaf(wv1, xv.x, acc1[u*4+0]);
                acc1[u*4+1] = fmaf(wv1, xv.y, acc1[u*4+1]);
                acc1[u*4+2] = fmaf(wv1, xv.z, acc1[u*4+2]);
                acc1[u*4+3] = fmaf(wv1, xv.w, acc1[u*4+3]);
            }
        }
        __syncthreads();
    }

    {
        float s0 = g1[mlo] * rsqrtf(v1[mlo] + EPSF);
        float bb0 = b1[mlo] - mu1[mlo] * s0;
        float s1 = g1[mlo + 128] * rsqrtf(v1[mlo + 128] + EPSF);
        float bb1 = b1[mlo + 128] - mu1[mlo + 128] * s1;
#pragma unroll
        for (int j = 0; j < 16; j++) {
            acc0[j] = fmaf(acc0[j], s0, bb0);
            acc1[j] = fmaf(acc1[j], s1, bb1);
        }
    }

    {
        float a00 = aw[mlo], a01 = aw[mlo + 128];
        float a10 = aw[256 + mlo], a11 = aw[256 + mlo + 128];
        float a20 = aw[512 + mlo], a21 = aw[512 + mlo + 128];
        float a30 = aw[768 + mlo], a31 = aw[768 + mlo + 128];
#pragma unroll
        for (int j = 0; j < 16; j++) {
            int p = pb + j;
            float yv0 = yu_s[mlo * 33 + p];
            float yv1 = yu_s[(mlo + 128) * 33 + p];
            float t0 = a00 * acc0[j] + a01 * acc1[j] + a10 * yv0 + a11 * yv1;
            float t1 = a20 * acc0[j] + a21 * acc1[j] + a30 * yv0 + a31 * yv1;
#pragma unroll
            for (int o = 16; o > 0; o >>= 1) {
                t0 += __shfl_xor_sync(0xffffffffu, t0, o);
                t1 += __shfl_xor_sync(0xffffffffu, t1, o);
            }
            if (lane == 0) {
                red[(wid * 16 + j) * 2 + 0] = t0;
                red[(wid * 16 + j) * 2 + 1] = t1;
            }
        }
    }
    __syncthreads();
    if (tid < 32) {
        int grp = tid >> 4, j = tid & 15;
        float s0 = 0.f, s1 = 0.f;
#pragma unroll
        for (int w = 0; w < 4; w++) {
            s0 += red[((grp * 4 + w) * 16 + j) * 2 + 0];
            s1 += red[((grp * 4 + w) * 16 + j) * 2 + 1];
        }
        zs[tid]      = 1.f / (1.f + expf(-(s0 + attb[0])));
        zs[32 + tid] = 1.f / (1.f + expf(-(s1 + attb[1])));
    }
    __syncthreads();

    float* xo0 = xf_nchw + ((size_t)(n * 256 + mlo)) * P_ + p0 + pb;
    float* xo1 = xf_nchw + ((size_t)(n * 256 + mlo + 128)) * P_ + p0 + pb;
    float* nh  = g_nhwc + ((size_t)n * P_ + p0 + pb) * 256;
#pragma unroll
    for (int j = 0; j < 16; j++) {
        int p = pb + j;
        float z0 = zs[p], z1 = zs[32 + p];
        float f0 = fmaf(acc0[j], z0, yu_s[mlo * 33 + p] * z1);
        float f1 = fmaf(acc1[j], z0, yu_s[(mlo + 128) * 33 + p] * z1);
        xo0[j] = f0;
        xo1[j] = f1;
        nh[(size_t)j * 256 + mlo] = f0;
        nh[(size_t)j * 256 + mlo + 128] = f1;
    }
}

// ---------------------------------------------------------------------------
// Kernel 2: offset conv3x3 (256 -> 18), pad 1. (unchanged from R2)
// ---------------------------------------------------------------------------
__global__ __launch_bounds__(256, 4)
void k2_off(const float* __restrict__ xf, const float* __restrict__ ow)
{
    __shared__ float xr[32 * 3 * 60];
    __shared__ float wr[18 * 289];

    const int h = blockIdx.x, n = blockIdx.y;
    const int tid = threadIdx.x;
    const int o = tid / 14, wg = tid % 14, wbase = wg * 4;

    float acc[4] = {0.f, 0.f, 0.f, 0.f};

    for (int c0 = 0; c0 < 256; c0 += 32) {
        for (int i = tid; i < 5568; i += 256) {
            int c = i / 174, rem = i % 174, r = rem / 58, colp = rem % 58;
            int row = h + r - 1, col = colp - 1;
            float v = 0.f;
            if (row >= 0 && row < 56 && col >= 0 && col < 56)
                v = xf[((size_t)(n * 256 + c0 + c)) * P_ + row * 56 + col];
            xr[c * 180 + r * 60 + colp] = v;
        }
        for (int i = tid; i < 5184; i += 256) {
            int oo = i / 288, rem = i % 288;
            wr[oo * 289 + rem] = ow[(size_t)oo * 2304 + c0 * 9 + rem];
        }
        __syncthreads();
        if (tid < 252) {
            for (int c = 0; c < 32; c++) {
#pragma unroll
                for (int ky = 0; ky < 3; ky++) {
                    const float4* rp = (const float4*)(xr + c * 180 + ky * 60 + wbase);
                    float4 A = rp[0], B = rp[1];
                    float xrow[6] = {A.x, A.y, A.z, A.w, B.x, B.y};
#pragma unroll
                    for (int kx = 0; kx < 3; kx++) {
                        float wv = wr[o * 289 + c * 9 + ky * 3 + kx];
#pragma unroll
                        for (int j = 0; j < 4; j++)
                            acc[j] = fmaf(wv, xrow[kx + j], acc[j]);
                    }
                }
            }
        }
        __syncthreads();
    }
    if (tid < 252) {
        float* ob = g_off + ((size_t)(n * 18 + o)) * P_ + h * 56 + wbase;
#pragma unroll
        for (int j = 0; j < 4; j++) ob[j] = acc[j];
    }
}

// ---------------------------------------------------------------------------
// Kernel 3: deformable conv via mma.sync tf32 (family-safe PTX).
// Tile = 56 px (one image row) x 256 outputs per block; grid (56, 8).
// K = 2304 as 72 double-buffered chunks of (tap kk, 32 channels).
// Warp w: o in [w*32, w*32+32), all 56 px. acc = 2 m-tiles x 7 n-tiles x 4.
// smem pitch 36 words -> conflict-free fragment LDS.
// ---------------------------------------------------------------------------
#define W_PITCH 36
#define S_PITCH 36
// float offsets inside dynamic smem
#define OFS_W    0                         // 2 x 256*36 = 18432
#define OFS_S    (OFS_W + 2*256*W_PITCH)   // 2 x 56*36  = 4032
#define OFS_MW   (OFS_S + 2*56*S_PITCH)    // 504*4 = 2016
#define OFS_MO   (OFS_MW + 2016)           // 2016
#define S3_FLOATS (OFS_MO + 2016)          // 26496 floats = 105984 B

__global__ __launch_bounds__(256, 2)
void k3_mma(const float* __restrict__ g2, const float* __restrict__ b2,
            const float* __restrict__ mu2, const float* __restrict__ v2,
            float* __restrict__ out)
{
    extern __shared__ float smf[];
    float*  wbuf = smf + OFS_W;
    float*  sbuf = smf + OFS_S;
    float4* mw4  = (float4*)(smf + OFS_MW);
    int4*   mo4  = (int4*)(smf + OFS_MO);

    const int n   = blockIdx.y;
    const int p0  = blockIdx.x * 56;
    const int tid = threadIdx.x;
    const int wid = tid >> 5;
    const int lane = tid & 31;

    // bilinear metadata: 56 px x 9 taps = 504 entries
    for (int e = tid; e < 504; e += 256) {
        int p = e / 9, k = e - p * 9;
        int pg = p0 + p;
        int ph = pg / 56, pw = pg % 56;
        float dy = g_off[((size_t)(n * 18 + 2 * k)) * P_ + pg];
        float dx = g_off[((size_t)(n * 18 + 2 * k + 1)) * P_ + pg];
        float sy = (float)(ph - 1 + k / 3) + dy;
        float sx = (float)(pw - 1 + k % 3) + dx;
        float y0f = floorf(sy), x0f = floorf(sx);
        float wy1 = sy - y0f, wx1 = sx - x0f;
        int iy0 = (int)y0f, ix0 = (int)x0f;
        bool vy0 = (iy0 >= 0) && (iy0 <= 55);
        bool vy1 = (iy0 + 1 >= 0) && (iy0 + 1 <= 55);
        bool vx0 = (ix0 >= 0) && (ix0 <= 55);
        bool vx1 = (ix0 + 1 >= 0) && (ix0 + 1 <= 55);
        int y0c = min(max(iy0, 0), 55),     y1c = min(max(iy0 + 1, 0), 55);
        int x0c = min(max(ix0, 0), 55),     x1c = min(max(ix0 + 1, 0), 55);
        float4 w;
        w.x = (vy0 && vx0) ? (1.f - wy1) * (1.f - wx1) : 0.f;
        w.y = (vy0 && vx1) ? (1.f - wy1) * wx1 : 0.f;
        w.z = (vy1 && vx0) ? wy1 * (1.f - wx1) : 0.f;
        w.w = (vy1 && vx1) ? wy1 * wx1 : 0.f;
        int4 oo;
        oo.x = (y0c * 56 + x0c) * 256;
        oo.y = (y0c * 56 + x1c) * 256;
        oo.z = (y1c * 56 + x0c) * 256;
        oo.w = (y1c * 56 + x1c) * 256;
        mw4[e] = w;
        mo4[e] = oo;
    }
    __syncthreads();

    const float* nh = g_nhwc + (size_t)n * P_ * 256;
    const int o0 = wid * 32;

    float acc[2][7][4];
#pragma unroll
    for (int m = 0; m < 2; m++)
#pragma unroll
        for (int t = 0; t < 7; t++)
#pragma unroll
            for (int c = 0; c < 4; c++) acc[m][t][c] = 0.f;

    auto fill_w = [&](int buf, int kk, int c0) {
        float* dst = wbuf + buf * (256 * W_PITCH);
        const float* src = g_wt + kk * 256 + c0;
#pragma unroll
        for (int t = 0; t < 8; t++) {
            int i = tid + t * 256;          // float4 index, 2048 total
            int o = i >> 3, seg = i & 7;
            float4 v = *(const float4*)(src + (size_t)o * 2304 + seg * 4);
            *(float4*)(dst + o * W_PITCH + seg * 4) = v;
        }
    };
    auto fill_s = [&](int buf, int kk, int c0) {
        float* dst = sbuf + buf * (56 * S_PITCH);
        int ci = c0 + lane;
#pragma unroll
        for (int it = 0; it < 7; it++) {
            int p = wid * 7 + it;
            int e = p * 9 + kk;
            float4 w = mw4[e];
            int4  oo = mo4[e];
            float v = w.x * nh[oo.x + ci] + w.y * nh[oo.y + ci]
                    + w.z * nh[oo.z + ci] + w.w * nh[oo.w + ci];
            dst[p * S_PITCH + lane] = to_tf32(v);
        }
    };

    fill_w(0, 0, 0);
    fill_s(0, 0, 0);
    __syncthreads();

    const int qrow = lane >> 2;   // 0..7
    const int qcol = lane & 3;    // 0..3

    for (int ch = 0; ch < 72; ch++) {
        int b = ch & 1;
        if (ch + 1 < 72) {
            int kk = (ch + 1) >> 3, cb = (ch + 1) & 7;
            fill_w(b ^ 1, kk, cb * 32);
            fill_s(b ^ 1, kk, cb * 32);
        }
        const float* Wb = wbuf + b * (256 * W_PITCH);
        const float* Sb = sbuf + b * (56 * S_PITCH);
#pragma unroll
        for (int s = 0; s < 4; s++) {
            int k0 = s * 8;
            uint32_t a[2][4];
            const float* wr = Wb + (o0 + qrow) * W_PITCH + k0 + qcol;
#pragma unroll
            for (int m = 0; m < 2; m++) {
                const float* wm = wr + m * 16 * W_PITCH;
                a[m][0] = __float_as_uint(wm[0]);
                a[m][1] = __float_as_uint(wm[8 * W_PITCH]);
                a[m][2] = __float_as_uint(wm[4]);
                a[m][3] = __float_as_uint(wm[8 * W_PITCH + 4]);
            }
            uint32_t bb[7][2];
            const float* sr = Sb + qrow * S_PITCH + k0 + qcol;
#pragma unroll
            for (int t = 0; t < 7; t++) {
                bb[t][0] = __float_as_uint(sr[t * 8 * S_PITCH]);
                bb[t][1] = __float_as_uint(sr[t * 8 * S_PITCH + 4]);
            }
#pragma unroll
            for (int m = 0; m < 2; m++)
#pragma unroll
                for (int t = 0; t < 7; t++)
                    mma_tf32(acc[m][t], a[m], bb[t]);
        }
        __syncthreads();
    }

    // epilogue: BN2 + store (c0,c1 pair -> STG.64)
#pragma unroll
    for (int m = 0; m < 2; m++) {
#pragma unroll
        for (int rh = 0; rh < 2; rh++) {
            int o = o0 + m * 16 + rh * 8 + qrow;
            float sc = g2[o] * rsqrtf(v2[o] + EPSF);
            float bi = b2[o] - mu2[o] * sc;
            float* ob = out + ((size_t)(n * 256 + o)) * P_ + p0;
#pragma unroll
            for (int t = 0; t < 7; t++) {
                float2 v;
                v.x = fmaf(acc[m][t][rh * 2 + 0], sc, bi);
                v.y = fmaf(acc[m][t][rh * 2 + 1], sc, bi);
                *(float2*)(ob + t * 8 + 2 * qcol) = v;
            }
        }
    }
}

// ---------------------------------------------------------------------------
extern "C" void kernel_launch(void* const* d_in, const int* in_sizes, int n_in,
                              void* d_out, int out_size)
{
    const float* x       = (const float*)d_in[0];
    const float* y       = (const float*)d_in[1];
    const float* conv1_w = (const float*)d_in[2];
    const float* bn1_g   = (const float*)d_in[3];
    const float* bn1_b   = (const float*)d_in[4];
    const float* bn1_m   = (const float*)d_in[5];
    const float* bn1_v   = (const float*)d_in[6];
    const float* att_w   = (const float*)d_in[7];
    const float* att_b   = (const float*)d_in[8];
    const float* off_w   = (const float*)d_in[9];
    const float* dcn_w   = (const float*)d_in[10];
    const float* bn2_g   = (const float*)d_in[11];
    const float* bn2_b   = (const float*)d_in[12];
    const float* bn2_m   = (const float*)d_in[13];
    const float* bn2_v   = (const float*)d_in[14];

    float* out = (float*)d_out;
    const size_t one = (size_t)N_ * OUTC * P_;  // 6,422,528

    float* xf_nchw;
    if ((size_t)out_size >= 2 * one) {
        xf_nchw = out + one;  // tuple (out, xf) flattened
    } else {
        void* p = nullptr;
        cudaGetSymbolAddress(&p, g_xf_scratch);
        xf_nchw = (float*)p;
    }

    cudaFuncSetAttribute(k1_fuse, cudaFuncAttributeMaxDynamicSharedMemorySize, 64 * 1024);
    cudaFuncSetAttribute(k3_mma,  cudaFuncAttributeMaxDynamicSharedMemorySize, S3_FLOATS * 4);

    k0_wt<<<256, 256>>>(dcn_w);

    const size_t smem1 = (512 + 4352 + 8448 + 1024 + 256 + 64) * 4; // 58,624
    k1_fuse<<<dim3(98, 8), 256, smem1>>>(x, y, conv1_w, bn1_g, bn1_b, bn1_m, bn1_v,
                                         att_w, att_b, xf_nchw);

    k2_off<<<dim3(56, 8), 256>>>(xf_nchw, off_w);

    k3_mma<<<dim3(56, 8), 256, S3_FLOATS * 4>>>(bn2_g, bn2_b, bn2_m, bn2_v, out);
}